// round 3
// baseline (speedup 1.0000x reference)
#include <cuda_runtime.h>
#include <cuda_bf16.h>
#include <cstdint>

// Problem constants
#define BATCH 16
#define CIN   64
#define COUT  128
#define HH    32
#define WW    32
#define HP    34            // padded
#define L     (HH*WW)       // 1024 pixels per image
#define KTAPS 9

#define XBLOCKS 132
#define WBLOCKS 16

// ---- device scratch (zero-initialized at module load; no allocations) ----
__device__ float g_part[XBLOCKS + WBLOCKS];        // per-block |max| partials
__device__ float g_oscale;
__device__ signed char g_qxp[BATCH*HP*HP*CIN];     // NHWC, zero-padded halo
__device__ signed char g_qw [KTAPS*COUT*CIN];      // [tap][cout][cin]

// ---------------------------------------------------------------------------
// 1) per-block max|v| partials over x (blocks 0..131) and w (132..147)
// ---------------------------------------------------------------------------
__global__ void __launch_bounds__(256) kmax(const float4* __restrict__ x,
                                            const float4* __restrict__ w) {
    __shared__ float sred[8];
    const int b = blockIdx.x;
    float m = 0.f;
    if (b < XBLOCKS) {
        const int n4 = BATCH*CIN*L/4;                       // 262144
        for (int i = b*256 + threadIdx.x; i < n4; i += XBLOCKS*256) {
            float4 v = x[i];
            m = fmaxf(m, fmaxf(fmaxf(fabsf(v.x), fabsf(v.y)),
                               fmaxf(fabsf(v.z), fabsf(v.w))));
        }
    } else {
        const int n4 = KTAPS*COUT*CIN/4;                    // 18432
        for (int i = (b-XBLOCKS)*256 + threadIdx.x; i < n4; i += WBLOCKS*256) {
            float4 v = w[i];
            m = fmaxf(m, fmaxf(fmaxf(fabsf(v.x), fabsf(v.y)),
                               fmaxf(fabsf(v.z), fabsf(v.w))));
        }
    }
    #pragma unroll
    for (int o = 16; o; o >>= 1) m = fmaxf(m, __shfl_xor_sync(~0u, m, o));
    if ((threadIdx.x & 31) == 0) sred[threadIdx.x >> 5] = m;
    __syncthreads();
    if (threadIdx.x < 8) {
        m = sred[threadIdx.x];
        #pragma unroll
        for (int o = 4; o; o >>= 1) m = fmaxf(m, __shfl_xor_sync(0xffu, m, o));
        if (threadIdx.x == 0) g_part[b] = m;
    }
}

// ---------------------------------------------------------------------------
// 2) fused scale + quantize x (blocks 0..63) and w (blocks 64..135)
// ---------------------------------------------------------------------------
__global__ void __launch_bounds__(256) kquant(const float* __restrict__ x,
                                              const float* __restrict__ w) {
    __shared__ float s_sc[2];
    const int tid = threadIdx.x, wid = tid >> 5, lane = tid & 31;
    if (wid == 0) {                      // reduce x partials (132)
        float m = 0.f;
        #pragma unroll
        for (int i = lane; i < XBLOCKS; i += 32) m = fmaxf(m, g_part[i]);
        #pragma unroll
        for (int o = 16; o; o >>= 1) m = fmaxf(m, __shfl_xor_sync(~0u, m, o));
        if (lane == 0) s_sc[0] = __fdiv_rn(m, 127.0f);
    } else if (wid == 1) {               // reduce w partials (16)
        float m = (lane < WBLOCKS) ? g_part[XBLOCKS + lane] : 0.f;
        #pragma unroll
        for (int o = 16; o; o >>= 1) m = fmaxf(m, __shfl_xor_sync(~0u, m, o));
        if (lane == 0) s_sc[1] = __fdiv_rn(m, 127.0f);
    }
    __syncthreads();
    const float xs = s_sc[0], ws = s_sc[1];
    if (blockIdx.x == 0 && tid == 0) g_oscale = __fmul_rn(xs, ws);

    if (blockIdx.x < 64) {
        // input: one thread per pixel, all 64 channels -> 64B coalesced store
        const int idx = blockIdx.x * 256 + tid;             // 0..16383
        const int pix = idx & (L - 1);
        const int b   = idx >> 10;
        const int y = pix >> 5, xc = pix & 31;
        const float* xp = x + ((size_t)b * CIN) * L + pix;
        signed char q[64];
        #pragma unroll
        for (int c = 0; c < 64; c++) {
            float r = rintf(__fdiv_rn(xp[(size_t)c * L], xs));
            r = fminf(fmaxf(r, -127.f), 127.f);
            q[c] = (signed char)(int)r;
        }
        int4* d = reinterpret_cast<int4*>(
            g_qxp + (((b*HP + y + 1)*HP + (xc + 1)) * CIN));
        const int4* s = reinterpret_cast<const int4*>(q);
        d[0] = s[0]; d[1] = s[1]; d[2] = s[2]; d[3] = s[3];
    } else {
        // weight [cout][cin][tap] -> g_qw[tap][cout][cin], char4 per thread
        const int idx = (blockIdx.x - 64) * 256 + tid;      // 0..18431
        const int cin4 = idx & 15;
        const int rem  = idx >> 4;
        const int cout = rem & 127;
        const int tap  = rem >> 7;
        char4 q;
        #pragma unroll
        for (int j = 0; j < 4; j++) {
            float r = rintf(__fdiv_rn(w[(cout*CIN + cin4*4 + j)*KTAPS + tap], ws));
            r = fminf(fmaxf(r, -127.f), 127.f);
            ((signed char*)&q)[j] = (signed char)(int)r;
        }
        *reinterpret_cast<char4*>(g_qw + (tap*COUT + cout)*CIN + cin4*4) = q;
    }
}

// ---------------------------------------------------------------------------
// 3) int8 GEMM-conv, mma.sync m16n8k32 s8s8s32, cp.async double-buffered A
// ---------------------------------------------------------------------------
#define ROWB 80                         // padded smem row stride (bytes)
#define BS_BYTES (KTAPS*COUT*ROWB)      // 92160
#define AS_HALF  (128*ROWB)             // 10240
#define SMEM_TOT (BS_BYTES + 2*AS_HALF) // 112640

__device__ __forceinline__ void mma_s8(int d[4], const unsigned a[4],
                                       unsigned b0, unsigned b1) {
    asm volatile(
      "mma.sync.aligned.m16n8k32.row.col.s32.s8.s8.s32 "
      "{%0,%1,%2,%3}, {%4,%5,%6,%7}, {%8,%9}, {%0,%1,%2,%3};\n"
      : "+r"(d[0]), "+r"(d[1]), "+r"(d[2]), "+r"(d[3])
      : "r"(a[0]), "r"(a[1]), "r"(a[2]), "r"(a[3]), "r"(b0), "r"(b1));
}

__device__ __forceinline__ void cp16(void* smem, const void* g) {
    unsigned s = (unsigned)__cvta_generic_to_shared(smem);
    asm volatile("cp.async.cg.shared.global [%0], [%1], 16;\n" :: "r"(s), "l"(g));
}

__global__ void __launch_bounds__(256, 1)
kgemm(const float* __restrict__ bias, float* __restrict__ out) {
    extern __shared__ char sm[];
    char* Bs = sm;                  // [9*128][80]
    char* As = sm + BS_BYTES;       // 2 x [128][80]

    const int tid   = threadIdx.x;
    const int wid   = tid >> 5;
    const int lane  = tid & 31;
    const int g     = lane >> 2;
    const int tg    = lane & 3;
    const int warpM = wid >> 1;
    const int warpN = wid & 1;

    const int bi    = blockIdx.x >> 3;
    const int ytile = blockIdx.x & 7;
    const int l0    = ytile * 128;

    // A-stage addressing: each thread cp.asyncs 2x16B of one row-half
    const int arow  = tid >> 1, ahalf = tid & 1;
    const int ay    = ytile * 4 + (arow >> 5);
    const int ax    = arow & 31;

    // stage full weight tile (once)
    for (int r = tid; r < KTAPS * COUT; r += 256) {
        const int4* s = reinterpret_cast<const int4*>(g_qw + r * CIN);
        int4* d = reinterpret_cast<int4*>(Bs + r * ROWB);
        d[0] = s[0]; d[1] = s[1]; d[2] = s[2]; d[3] = s[3];
    }

    // prefetch A for tap 0
    {
        const signed char* src =
            g_qxp + (((bi*HP + ay + 0)*HP + (ax + 0))*CIN) + ahalf*32;
        char* dst = As + arow * ROWB + ahalf*32;
        cp16(dst, src); cp16(dst + 16, src + 16);
        asm volatile("cp.async.commit_group;\n");
    }

    int acc[2][8][4];
    #pragma unroll
    for (int mi = 0; mi < 2; mi++)
        #pragma unroll
        for (int nb = 0; nb < 8; nb++)
            #pragma unroll
            for (int r = 0; r < 4; r++) acc[mi][nb][r] = 0;

    asm volatile("cp.async.wait_group 0;\n");
    __syncthreads();

    for (int tap = 0; tap < KTAPS; tap++) {
        if (tap < 8) {   // prefetch next tap into other buffer
            const int kh = (tap+1) / 3, kw = (tap+1) % 3;
            const signed char* src =
                g_qxp + (((bi*HP + ay + kh)*HP + (ax + kw))*CIN) + ahalf*32;
            char* dst = As + ((tap+1)&1)*AS_HALF + arow * ROWB + ahalf*32;
            cp16(dst, src); cp16(dst + 16, src + 16);
            asm volatile("cp.async.commit_group;\n");
        }
        const char* Ab = As + (tap&1)*AS_HALF;

        #pragma unroll
        for (int kk = 0; kk < 2; kk++) {
            const int ko = kk * 32;
            unsigned a[2][4];
            #pragma unroll
            for (int mi = 0; mi < 2; mi++) {
                const int rb = warpM*32 + mi*16 + g;
                a[mi][0] = *reinterpret_cast<const unsigned*>(Ab + rb*ROWB     + ko + tg*4);
                a[mi][1] = *reinterpret_cast<const unsigned*>(Ab + (rb+8)*ROWB + ko + tg*4);
                a[mi][2] = *reinterpret_cast<const unsigned*>(Ab + rb*ROWB     + ko + 16 + tg*4);
                a[mi][3] = *reinterpret_cast<const unsigned*>(Ab + (rb+8)*ROWB + ko + 16 + tg*4);
            }
            #pragma unroll
            for (int nb = 0; nb < 8; nb++) {
                const int n = warpN*64 + nb*8 + g;
                const char* bp = Bs + (tap*COUT + n)*ROWB + ko + tg*4;
                unsigned b0 = *reinterpret_cast<const unsigned*>(bp);
                unsigned b1 = *reinterpret_cast<const unsigned*>(bp + 16);
                mma_s8(acc[0][nb], a[0], b0, b1);
                mma_s8(acc[1][nb], a[1], b0, b1);
            }
        }
        if (tap < 8) asm volatile("cp.async.wait_group 0;\n");
        __syncthreads();
    }

    // epilogue: out[b][cout][l] = oscale*acc + bias[cout]
    const float scale = g_oscale;
    #pragma unroll
    for (int mi = 0; mi < 2; mi++) {
        #pragma unroll
        for (int nb = 0; nb < 8; nb++) {
            const int n   = warpN*64 + nb*8 + tg*2;
            const float bz0 = bias[n], bz1 = bias[n+1];
            #pragma unroll
            for (int r = 0; r < 4; r++) {
                const int row = warpM*32 + mi*16 + g + ((r >> 1) * 8);
                const int col = n + (r & 1);
                out[(bi*COUT + col)*L + l0 + row] =
                    scale * (float)acc[mi][nb][r] + ((r & 1) ? bz1 : bz0);
            }
        }
    }
}

// ---------------------------------------------------------------------------
extern "C" void kernel_launch(void* const* d_in, const int* in_sizes, int n_in,
                              void* d_out, int out_size) {
    const float* x  = (const float*)d_in[0];   // [16,64,32,32]
    const float* w  = (const float*)d_in[1];   // [128,64,3,3]
    const float* bs = (const float*)d_in[2];   // [128]
    float* out = (float*)d_out;                // [16,128,32,32]

    cudaFuncSetAttribute(kgemm, cudaFuncAttributeMaxDynamicSharedMemorySize,
                         SMEM_TOT);

    kmax<<<XBLOCKS + WBLOCKS, 256>>>((const float4*)x, (const float4*)w);
    kquant<<<136, 256>>>(x, w);
    kgemm<<<BATCH*8, 256, SMEM_TOT>>>(bs, out);
}

// round 4
// speedup vs baseline: 1.2090x; 1.2090x over previous
#include <cuda_runtime.h>
#include <cuda_bf16.h>
#include <cstdint>

// Problem constants
#define BATCH 16
#define CIN   64
#define COUT  128
#define HP    34            // padded
#define L     1024          // 32*32 pixels per image
#define KTAPS 9

#define NBLK  128
#define NTHR  256
#define NT    (NBLK*NTHR)   // 32768 threads

// ---- device scratch (zero-initialized at module load; no allocations) ----
__device__ float g_partx[NBLK];
__device__ float g_partw[NBLK];
__device__ signed char g_qxp[BATCH*HP*HP*CIN];     // NHWC, zero-padded halo
__device__ signed char g_qw [KTAPS*COUT*CIN];      // [tap][cout][cin]
__device__ volatile unsigned g_cnt;                // grid barrier state
__device__ volatile unsigned g_gen;

// replay-safe sense-reversing grid barrier (all NBLK blocks resident)
__device__ __forceinline__ void gridbar() {
    __syncthreads();
    if (threadIdx.x == 0) {
        unsigned gen = g_gen;
        __threadfence();
        unsigned t = atomicInc((unsigned*)&g_cnt, NBLK - 1);   // wraps to 0
        if (t == NBLK - 1) atomicAdd((unsigned*)&g_gen, 1);
        else while (g_gen == gen) {}
        __threadfence();
    }
    __syncthreads();
}

// ---------------------------------------------------------------------------
// GEMM smem layout
// ---------------------------------------------------------------------------
#define ROWB 80                         // padded smem row stride (bytes)
#define BS_BYTES (KTAPS*COUT*ROWB)      // 92160
#define AS_HALF  (128*ROWB)             // 10240
#define SMEM_TOT (BS_BYTES + 2*AS_HALF) // 112640

__device__ __forceinline__ void mma_s8(int d[4], const unsigned a[4],
                                       unsigned b0, unsigned b1) {
    asm volatile(
      "mma.sync.aligned.m16n8k32.row.col.s32.s8.s8.s32 "
      "{%0,%1,%2,%3}, {%4,%5,%6,%7}, {%8,%9}, {%0,%1,%2,%3};\n"
      : "+r"(d[0]), "+r"(d[1]), "+r"(d[2]), "+r"(d[3])
      : "r"(a[0]), "r"(a[1]), "r"(a[2]), "r"(a[3]), "r"(b0), "r"(b1));
}

__device__ __forceinline__ void cp16(void* smem, const void* g) {
    unsigned s = (unsigned)__cvta_generic_to_shared(smem);
    asm volatile("cp.async.cg.shared.global [%0], [%1], 16;\n" :: "r"(s), "l"(g));
}

__global__ void __launch_bounds__(NTHR, 1)
kfused(const float* __restrict__ x, const float* __restrict__ w,
       const float* __restrict__ bias, float* __restrict__ out) {
    extern __shared__ char sm[];
    __shared__ float srx[8], srw[8], s_sc[2];

    const int tid  = threadIdx.x;
    const int wid  = tid >> 5;
    const int lane = tid & 31;
    const int t    = blockIdx.x * NTHR + tid;      // 0..32767

    // ---------------- phase 1: max|x|, max|w| ----------------
    {
        const float4* x4 = reinterpret_cast<const float4*>(x);
        const float4* w4 = reinterpret_cast<const float4*>(w);
        float mx = 0.f;
        #pragma unroll
        for (int u = 0; u < 8; u++) {              // 262144 float4 of x
            float4 v = x4[t + NT*u];
            mx = fmaxf(mx, fmaxf(fmaxf(fabsf(v.x), fabsf(v.y)),
                                 fmaxf(fabsf(v.z), fabsf(v.w))));
        }
        float mw = 0.f;
        if (t < KTAPS*COUT*CIN/4) {                // 18432 float4 of w
            float4 v = w4[t];
            mw = fmaxf(fmaxf(fabsf(v.x), fabsf(v.y)),
                       fmaxf(fabsf(v.z), fabsf(v.w)));
        }
        #pragma unroll
        for (int o = 16; o; o >>= 1) {
            mx = fmaxf(mx, __shfl_xor_sync(~0u, mx, o));
            mw = fmaxf(mw, __shfl_xor_sync(~0u, mw, o));
        }
        if (lane == 0) { srx[wid] = mx; srw[wid] = mw; }
        __syncthreads();
        if (tid < 8) {
            mx = srx[tid]; mw = srw[tid];
            #pragma unroll
            for (int o = 4; o; o >>= 1) {
                mx = fmaxf(mx, __shfl_xor_sync(0xffu, mx, o));
                mw = fmaxf(mw, __shfl_xor_sync(0xffu, mw, o));
            }
            if (tid == 0) { g_partx[blockIdx.x] = mx; g_partw[blockIdx.x] = mw; }
        }
    }
    gridbar();

    // ---------------- phase 2: scales + quantize ----------------
    if (wid == 0) {
        float m = fmaxf(fmaxf(g_partx[lane], g_partx[lane+32]),
                        fmaxf(g_partx[lane+64], g_partx[lane+96]));
        #pragma unroll
        for (int o = 16; o; o >>= 1) m = fmaxf(m, __shfl_xor_sync(~0u, m, o));
        if (lane == 0) s_sc[0] = __fdiv_rn(m, 127.0f);
    } else if (wid == 1) {
        float m = fmaxf(fmaxf(g_partw[lane], g_partw[lane+32]),
                        fmaxf(g_partw[lane+64], g_partw[lane+96]));
        #pragma unroll
        for (int o = 16; o; o >>= 1) m = fmaxf(m, __shfl_xor_sync(~0u, m, o));
        if (lane == 0) s_sc[1] = __fdiv_rn(m, 127.0f);
    }
    __syncthreads();
    const float xs = s_sc[0], ws = s_sc[1];
    const float oscale = __fmul_rn(xs, ws);

    // quantize x: 8 char4-units per thread, coalesced char4 stores
    #pragma unroll
    for (int u = 0; u < 8; u++) {
        const int idx = t + NT*u;                  // 0..262143
        const int pix = idx & (L-1);
        const int c4  = (idx >> 10) & 15;
        const int b   = idx >> 14;
        const int y = pix >> 5, xc = pix & 31;
        char4 q;
        #pragma unroll
        for (int j = 0; j < 4; j++) {
            float v = x[((b*CIN + c4*4 + j) << 10) + pix];
            float r = rintf(__fdiv_rn(v, xs));
            r = fminf(fmaxf(r, -127.f), 127.f);
            ((signed char*)&q)[j] = (signed char)(int)r;
        }
        *reinterpret_cast<char4*>(
            g_qxp + (((b*HP + y + 1)*HP + (xc + 1))*CIN + c4*4)) = q;
    }
    // quantize w: [cout][cin][tap] -> [tap][cout][cin]
    if (t < KTAPS*COUT*CIN/4) {
        const int cin4 = t & 15;
        const int rem  = t >> 4;
        const int cout = rem & 127;
        const int tap  = rem >> 7;
        char4 q;
        #pragma unroll
        for (int j = 0; j < 4; j++) {
            float r = rintf(__fdiv_rn(w[(cout*CIN + cin4*4 + j)*KTAPS + tap], ws));
            r = fminf(fmaxf(r, -127.f), 127.f);
            ((signed char*)&q)[j] = (signed char)(int)r;
        }
        *reinterpret_cast<char4*>(g_qw + (tap*COUT + cout)*CIN + cin4*4) = q;
    }
    gridbar();

    // ---------------- phase 3: int8 GEMM-conv ----------------
    char* Bs = sm;                  // [9*128][80]
    char* As = sm + BS_BYTES;       // 2 x [128][80]

    const int g     = lane >> 2;
    const int tg    = lane & 3;
    const int warpM = wid >> 1;
    const int warpN = wid & 1;

    const int bi    = blockIdx.x >> 3;
    const int ytile = blockIdx.x & 7;
    const int l0    = ytile * 128;

    const int arow  = tid >> 1, ahalf = tid & 1;
    const int ay    = ytile * 4 + (arow >> 5);
    const int ax    = arow & 31;

    // stage full weight tile
    for (int r = tid; r < KTAPS * COUT; r += NTHR) {
        const int4* s = reinterpret_cast<const int4*>(g_qw + r * CIN);
        int4* d = reinterpret_cast<int4*>(Bs + r * ROWB);
        d[0] = s[0]; d[1] = s[1]; d[2] = s[2]; d[3] = s[3];
    }
    // prefetch A for tap 0
    {
        const signed char* src =
            g_qxp + (((bi*HP + ay)*HP + ax)*CIN) + ahalf*32;
        char* dst = As + arow * ROWB + ahalf*32;
        cp16(dst, src); cp16(dst + 16, src + 16);
        asm volatile("cp.async.commit_group;\n");
    }

    int acc[2][8][4];
    #pragma unroll
    for (int mi = 0; mi < 2; mi++)
        #pragma unroll
        for (int nb = 0; nb < 8; nb++)
            #pragma unroll
            for (int r = 0; r < 4; r++) acc[mi][nb][r] = 0;

    asm volatile("cp.async.wait_group 0;\n");
    __syncthreads();

    for (int tap = 0; tap < KTAPS; tap++) {
        if (tap < 8) {
            const int kh = (tap+1) / 3, kw = (tap+1) % 3;
            const signed char* src =
                g_qxp + (((bi*HP + ay + kh)*HP + (ax + kw))*CIN) + ahalf*32;
            char* dst = As + ((tap+1)&1)*AS_HALF + arow * ROWB + ahalf*32;
            cp16(dst, src); cp16(dst + 16, src + 16);
            asm volatile("cp.async.commit_group;\n");
        }
        const char* Ab = As + (tap&1)*AS_HALF;

        #pragma unroll
        for (int kk = 0; kk < 2; kk++) {
            const int ko = kk * 32;
            unsigned a[2][4];
            #pragma unroll
            for (int mi = 0; mi < 2; mi++) {
                const int rb = warpM*32 + mi*16 + g;
                a[mi][0] = *reinterpret_cast<const unsigned*>(Ab + rb*ROWB     + ko + tg*4);
                a[mi][1] = *reinterpret_cast<const unsigned*>(Ab + (rb+8)*ROWB + ko + tg*4);
                a[mi][2] = *reinterpret_cast<const unsigned*>(Ab + rb*ROWB     + ko + 16 + tg*4);
                a[mi][3] = *reinterpret_cast<const unsigned*>(Ab + (rb+8)*ROWB + ko + 16 + tg*4);
            }
            #pragma unroll
            for (int nb = 0; nb < 8; nb++) {
                const int n = warpN*64 + nb*8 + g;
                const char* bp = Bs + (tap*COUT + n)*ROWB + ko + tg*4;
                unsigned b0 = *reinterpret_cast<const unsigned*>(bp);
                unsigned b1 = *reinterpret_cast<const unsigned*>(bp + 16);
                mma_s8(acc[0][nb], a[0], b0, b1);
                mma_s8(acc[1][nb], a[1], b0, b1);
            }
        }
        if (tap < 8) asm volatile("cp.async.wait_group 0;\n");
        __syncthreads();
    }

    // epilogue
    #pragma unroll
    for (int mi = 0; mi < 2; mi++) {
        #pragma unroll
        for (int nb = 0; nb < 8; nb++) {
            const int n   = warpN*64 + nb*8 + tg*2;
            const float bz0 = bias[n], bz1 = bias[n+1];
            #pragma unroll
            for (int r = 0; r < 4; r++) {
                const int row = warpM*32 + mi*16 + g + ((r >> 1) * 8);
                const int col = n + (r & 1);
                out[(bi*COUT + col)*L + l0 + row] =
                    oscale * (float)acc[mi][nb][r] + ((r & 1) ? bz1 : bz0);
            }
        }
    }
}

// ---------------------------------------------------------------------------
extern "C" void kernel_launch(void* const* d_in, const int* in_sizes, int n_in,
                              void* d_out, int out_size) {
    const float* x  = (const float*)d_in[0];   // [16,64,32,32]
    const float* w  = (const float*)d_in[1];   // [128,64,3,3]
    const float* bs = (const float*)d_in[2];   // [128]
    float* out = (float*)d_out;                // [16,128,32,32]

    cudaFuncSetAttribute(kfused, cudaFuncAttributeMaxDynamicSharedMemorySize,
                         SMEM_TOT);
    kfused<<<NBLK, NTHR, SMEM_TOT>>>(x, w, bs, out);
}

// round 6
// speedup vs baseline: 1.2760x; 1.0554x over previous
#include <cuda_runtime.h>
#include <cuda_bf16.h>
#include <cstdint>

// Problem constants
#define BATCH 16
#define CIN   64
#define COUT  128
#define HP    34            // padded
#define L     1024          // 32*32 pixels per image
#define KTAPS 9

#define NBLK  128
#define NTHR  512
#define NT    (NBLK*NTHR)   // 65536 threads

// ---- device scratch (zero-initialized at module load; no allocations) ----
__device__ float g_partx[NBLK];
__device__ float g_partw[NBLK];
__device__ signed char g_qxp[BATCH*HP*HP*CIN];     // NHWC, zero-padded halo
__device__ signed char g_qw [KTAPS*COUT*CIN];      // [tap][cout][cin]
__device__ volatile unsigned g_cnt;                // grid barrier state
__device__ volatile unsigned g_gen;

// replay-safe grid barrier (all NBLK blocks resident: 128 <= 148 SMs, 1 CTA/SM)
__device__ __forceinline__ void gridbar() {
    __syncthreads();
    if (threadIdx.x == 0) {
        unsigned gen = g_gen;
        __threadfence();
        unsigned t = atomicInc((unsigned*)&g_cnt, NBLK - 1);   // wraps to 0
        if (t == NBLK - 1) atomicAdd((unsigned*)&g_gen, 1);
        else while (g_gen == gen) {}
        __threadfence();
    }
    __syncthreads();
}

// ---------------------------------------------------------------------------
// GEMM smem layout
// ---------------------------------------------------------------------------
#define ROWB 80                         // padded smem row stride (bytes)
#define BS_BYTES (KTAPS*COUT*ROWB)      // 92160
#define AS_HALF  (128*ROWB)             // 10240
#define SMEM_TOT (BS_BYTES + 2*AS_HALF) // 112640
#define EP_STRIDE 132                   // epilogue smem stride (floats)

__device__ __forceinline__ void mma_s8(int d[4], const unsigned a[4],
                                       unsigned b0, unsigned b1) {
    asm volatile(
      "mma.sync.aligned.m16n8k32.row.col.s32.s8.s8.s32 "
      "{%0,%1,%2,%3}, {%4,%5,%6,%7}, {%8,%9}, {%0,%1,%2,%3};\n"
      : "+r"(d[0]), "+r"(d[1]), "+r"(d[2]), "+r"(d[3])
      : "r"(a[0]), "r"(a[1]), "r"(a[2]), "r"(a[3]), "r"(b0), "r"(b1));
}

__device__ __forceinline__ void cp16(void* smem, const void* g) {
    unsigned s = (unsigned)__cvta_generic_to_shared(smem);
    asm volatile("cp.async.cg.shared.global [%0], [%1], 16;\n" :: "r"(s), "l"(g));
}

__global__ void __launch_bounds__(NTHR, 1)
kfused(const float* __restrict__ x, const float* __restrict__ w,
       const float* __restrict__ bias, float* __restrict__ out) {
    extern __shared__ char sm[];
    __shared__ float srx[16], srw[16], s_sc[2];

    const int tid  = threadIdx.x;
    const int wid  = tid >> 5;
    const int lane = tid & 31;
    const int t    = blockIdx.x * NTHR + tid;      // 0..65535

    // ---------------- phase 1: max|x|, max|w| ----------------
    {
        const float4* x4 = reinterpret_cast<const float4*>(x);
        const float4* w4 = reinterpret_cast<const float4*>(w);
        float mx = 0.f;
        #pragma unroll
        for (int u = 0; u < 4; u++) {              // 262144 float4 of x
            float4 v = x4[t + NT*u];
            mx = fmaxf(mx, fmaxf(fmaxf(fabsf(v.x), fabsf(v.y)),
                                 fmaxf(fabsf(v.z), fabsf(v.w))));
        }
        float mw = 0.f;
        if (t < KTAPS*COUT*CIN/4) {                // 18432 float4 of w
            float4 v = w4[t];
            mw = fmaxf(fmaxf(fabsf(v.x), fabsf(v.y)),
                       fmaxf(fabsf(v.z), fabsf(v.w)));
        }
        #pragma unroll
        for (int o = 16; o; o >>= 1) {
            mx = fmaxf(mx, __shfl_xor_sync(~0u, mx, o));
            mw = fmaxf(mw, __shfl_xor_sync(~0u, mw, o));
        }
        if (lane == 0) { srx[wid] = mx; srw[wid] = mw; }
        __syncthreads();
        if (tid < 16) {
            mx = srx[tid]; mw = srw[tid];
            #pragma unroll
            for (int o = 8; o; o >>= 1) {
                mx = fmaxf(mx, __shfl_xor_sync(0xffffu, mx, o));
                mw = fmaxf(mw, __shfl_xor_sync(0xffffu, mw, o));
            }
            if (tid == 0) { g_partx[blockIdx.x] = mx; g_partw[blockIdx.x] = mw; }
        }
    }
    gridbar();

    // ---------------- phase 2: scales + quantize ----------------
    if (wid == 0) {
        float m = fmaxf(fmaxf(g_partx[lane], g_partx[lane+32]),
                        fmaxf(g_partx[lane+64], g_partx[lane+96]));
        #pragma unroll
        for (int o = 16; o; o >>= 1) m = fmaxf(m, __shfl_xor_sync(~0u, m, o));
        if (lane == 0) s_sc[0] = __fdiv_rn(m, 127.0f);
    } else if (wid == 1) {
        float m = fmaxf(fmaxf(g_partw[lane], g_partw[lane+32]),
                        fmaxf(g_partw[lane+64], g_partw[lane+96]));
        #pragma unroll
        for (int o = 16; o; o >>= 1) m = fmaxf(m, __shfl_xor_sync(~0u, m, o));
        if (lane == 0) s_sc[1] = __fdiv_rn(m, 127.0f);
    }
    __syncthreads();
    const float xs = s_sc[0], ws = s_sc[1];
    const float oscale = __fmul_rn(xs, ws);

    // quantize x: 4 char4-units per thread, coalesced char4 stores
    #pragma unroll
    for (int u = 0; u < 4; u++) {
        const int idx = t + NT*u;                  // 0..262143
        const int pix = idx & (L-1);
        const int c4  = (idx >> 10) & 15;
        const int b   = idx >> 14;
        const int y = pix >> 5, xc = pix & 31;
        char4 q;
        #pragma unroll
        for (int j = 0; j < 4; j++) {
            float v = x[((b*CIN + c4*4 + j) << 10) + pix];
            float r = rintf(__fdiv_rn(v, xs));
            r = fminf(fmaxf(r, -127.f), 127.f);
            ((signed char*)&q)[j] = (signed char)(int)r;
        }
        *reinterpret_cast<char4*>(
            g_qxp + (((b*HP + y + 1)*HP + (xc + 1))*CIN + c4*4)) = q;
    }
    // quantize w: [cout][cin][tap] -> [tap][cout][cin]
    if (t < KTAPS*COUT*CIN/4) {
        const int cin4 = t & 15;
        const int rem  = t >> 4;
        const int cout = rem & 127;
        const int tap  = rem >> 7;
        char4 q;
        #pragma unroll
        for (int j = 0; j < 4; j++) {
            float r = rintf(__fdiv_rn(w[(cout*CIN + cin4*4 + j)*KTAPS + tap], ws));
            r = fminf(fmaxf(r, -127.f), 127.f);
            ((signed char*)&q)[j] = (signed char)(int)r;
        }
        *reinterpret_cast<char4*>(g_qw + (tap*COUT + cout)*CIN + cin4*4) = q;
    }
    gridbar();

    // ---------------- phase 3: int8 GEMM-conv (16 warps, 32x32 warp tile) ---
    char* Bs = sm;                  // [9*128][80]
    char* As = sm + BS_BYTES;       // 2 x [128][80]

    const int g     = lane >> 2;
    const int tg    = lane & 3;
    const int warpM = wid >> 2;     // 0..3 -> 32 rows
    const int warpN = wid & 3;      // 0..3 -> 32 couts

    const int bi    = blockIdx.x >> 3;
    const int ytile = blockIdx.x & 7;
    const int l0    = ytile * 128;

    // A-stage addressing: 512 threads, one 16B cp.async each (128 rows x 64B)
    const int arow  = tid >> 2, aq = tid & 3;
    const int ay    = ytile * 4 + (arow >> 5);
    const int ax    = arow & 31;

    // stage full weight tile
    for (int r = tid; r < KTAPS * COUT; r += NTHR) {
        const int4* s = reinterpret_cast<const int4*>(g_qw + r * CIN);
        int4* d = reinterpret_cast<int4*>(Bs + r * ROWB);
        d[0] = s[0]; d[1] = s[1]; d[2] = s[2]; d[3] = s[3];
    }
    // prefetch A for tap 0
    {
        const signed char* src = g_qxp + (((bi*HP + ay)*HP + ax)*CIN) + aq*16;
        cp16(As + arow * ROWB + aq*16, src);
        asm volatile("cp.async.commit_group;\n");
    }

    int acc[2][4][4];
    #pragma unroll
    for (int mi = 0; mi < 2; mi++)
        #pragma unroll
        for (int nb = 0; nb < 4; nb++)
            #pragma unroll
            for (int r = 0; r < 4; r++) acc[mi][nb][r] = 0;

    asm volatile("cp.async.wait_group 0;\n");
    __syncthreads();

    for (int tap = 0; tap < KTAPS; tap++) {
        if (tap < 8) {
            const int kh = (tap+1) / 3, kw = (tap+1) % 3;
            const signed char* src =
                g_qxp + (((bi*HP + ay + kh)*HP + (ax + kw))*CIN) + aq*16;
            cp16(As + ((tap+1)&1)*AS_HALF + arow * ROWB + aq*16, src);
            asm volatile("cp.async.commit_group;\n");
        }
        const char* Ab = As + (tap&1)*AS_HALF;

        #pragma unroll
        for (int kk = 0; kk < 2; kk++) {
            const int ko = kk * 32;
            unsigned a[2][4];
            #pragma unroll
            for (int mi = 0; mi < 2; mi++) {
                const int rb = warpM*32 + mi*16 + g;
                a[mi][0] = *reinterpret_cast<const unsigned*>(Ab + rb*ROWB     + ko + tg*4);
                a[mi][1] = *reinterpret_cast<const unsigned*>(Ab + (rb+8)*ROWB + ko + tg*4);
                a[mi][2] = *reinterpret_cast<const unsigned*>(Ab + rb*ROWB     + ko + 16 + tg*4);
                a[mi][3] = *reinterpret_cast<const unsigned*>(Ab + (rb+8)*ROWB + ko + 16 + tg*4);
            }
            #pragma unroll
            for (int nb = 0; nb < 4; nb++) {
                const int n = warpN*32 + nb*8 + g;
                const char* bp = Bs + (tap*COUT + n)*ROWB + ko + tg*4;
                unsigned b0 = *reinterpret_cast<const unsigned*>(bp);
                unsigned b1 = *reinterpret_cast<const unsigned*>(bp + 16);
                mma_s8(acc[0][nb], a[0], b0, b1);
                mma_s8(acc[1][nb], a[1], b0, b1);
            }
        }
        if (tap < 8) asm volatile("cp.async.wait_group 0;\n");
        __syncthreads();
    }

    // ---------------- epilogue: smem transpose -> coalesced stores ----------
    // smem layout [col][row], stride EP_STRIDE floats: writes & reads conflict-free
    float* smf = reinterpret_cast<float*>(sm);     // 128*132*4 = 67584 <= SMEM_TOT
    #pragma unroll
    for (int mi = 0; mi < 2; mi++) {
        #pragma unroll
        for (int nb = 0; nb < 4; nb++) {
            #pragma unroll
            for (int r = 0; r < 4; r++) {
                const int row = warpM*32 + mi*16 + g + ((r >> 1) * 8);
                const int col = warpN*32 + nb*8 + tg*2 + (r & 1);
                smf[col*EP_STRIDE + row] = (float)acc[mi][nb][r];
            }
        }
    }
    __syncthreads();
    {
        // warp wid -> couts wid*8..wid*8+7; 32 consecutive pixels per store
        float* op = out + (size_t)bi*COUT*L + l0;
        #pragma unroll
        for (int co = 0; co < 8; co++) {
            const int cout = wid*8 + co;
            const float bz = bias[cout];
            #pragma unroll
            for (int j = 0; j < 4; j++) {
                const int pix = j*32 + lane;
                op[(size_t)cout*L + pix] =
                    oscale * smf[cout*EP_STRIDE + pix] + bz;
            }
        }
    }
}

// ---------------------------------------------------------------------------
extern "C" void kernel_launch(void* const* d_in, const int* in_sizes, int n_in,
                              void* d_out, int out_size) {
    const float* x  = (const float*)d_in[0];   // [16,64,32,32]
    const float* w  = (const float*)d_in[1];   // [128,64,3,3]
    const float* bs = (const float*)d_in[2];   // [128]
    float* out = (float*)d_out;                // [16,128,32,32]

    cudaFuncSetAttribute(kfused, cudaFuncAttributeMaxDynamicSharedMemorySize,
                         SMEM_TOT);
    kfused<<<NBLK, NTHR, SMEM_TOT>>>(x, w, bs, out);
}